// round 8
// baseline (speedup 1.0000x reference)
#include <cuda_runtime.h>
#include <cuda_bf16.h>
#include <cstdint>

// Problem shapes (fixed by the dataset)
#define S_LEN 2048
#define BATCH 16
#define DDIM  2048

// Stage-1 decomposition: 16 o-chunks x 16 k-parts = 256 blocks
#define NCH    16                  // o-chunks
#define OCH    128                 // o rows per chunk
#define KPARTS 16                  // k-parts per chunk
#define KCH    (DDIM / KPARTS)     // 128 d per part
#define KSUB   32                  // d per smem subtile
#define NSUB   (KCH / KSUB)        // 4
#define WPAD   33                  // sW bank = (t + d) % 32 -> conflict-free

// Scratch (device globals: allocation-free).
__device__ float g_part[NCH * KPARTS * OCH * BATCH];  // [c][kc][o][b], 2 MB
__device__ float g_altered[BATCH * DDIM];             // [b][o], 128 KB
__device__ int   g_cnt[NCH];                          // zero-init; self-resetting

__device__ __forceinline__ void ffma2(uint64_t& d, uint64_t a, uint64_t b) {
    asm("fma.rn.f32x2 %0, %1, %2, %0;" : "+l"(d) : "l"(a), "l"(b));
}

// ---------------------------------------------------------------------------
// Stage 1 (fused): 256 blocks, each computes one (o-chunk, k-part) partial.
// The 16th finisher per o-chunk (atomic ticket) reduces that chunk in fixed
// kc order (deterministic), adds bias, writes g_altered, resets the counter.
// No spin-waits anywhere -> no deadlock risk, works at any residency.
// ---------------------------------------------------------------------------
__global__ void __launch_bounds__(128)
stage1_fused(const float* __restrict__ state,
             const float* __restrict__ W,
             const float* __restrict__ bias)
{
    __shared__ float sW[OCH][WPAD];     // 16.9 KB
    __shared__ float sS[KSUB][BATCH];   // 2 KB
    __shared__ int   s_ticket;

    const int t     = threadIdx.x;      // 0..127 = local o
    const int c     = blockIdx.x & (NCH - 1);
    const int kc    = blockIdx.x >> 4;
    const int obase = c * OCH;
    const int d0    = kc * KCH;

    uint64_t acc[8];                    // 16 batch accs as packed f32x2
#pragma unroll
    for (int i = 0; i < 8; ++i) acc[i] = 0ull;

#pragma unroll
    for (int sc = 0; sc < NSUB; ++sc) {
        const int dd0 = d0 + sc * KSUB;

        // Stage state subtile transposed: sS[d][b]. Coalesced float4 LDG.
        {
            const int b  = t >> 3;
            const int c4 = t & 7;
            const float4 v = *(const float4*)(state + b * DDIM + dd0 + c4 * 4);
            sS[c4 * 4 + 0][b] = v.x;
            sS[c4 * 4 + 1][b] = v.y;
            sS[c4 * 4 + 2][b] = v.z;
            sS[c4 * 4 + 3][b] = v.w;
        }

        // Stage W subtile 128 rows x 32 d: 1024 float4, 8/thread, coalesced
        // (8 lanes/row -> nL=4); STS banks (r + 4*c4 + k) % 32 conflict-free.
#pragma unroll
        for (int j = 0; j < 8; ++j) {
            const int g  = j * 128 + t;
            const int r  = g >> 3;
            const int c4 = g & 7;
            const float4 v = *(const float4*)(W + (long)(obase + r) * DDIM + dd0 + c4 * 4);
            sW[r][c4 * 4 + 0] = v.x;
            sW[r][c4 * 4 + 1] = v.y;
            sW[r][c4 * 4 + 2] = v.z;
            sW[r][c4 * 4 + 3] = v.w;
        }
        __syncthreads();

#pragma unroll 8
        for (int d = 0; d < KSUB; ++d) {
            const float w = sW[t][d];                 // bank (t+d)%32
            uint64_t wp;
            asm("mov.b64 %0, {%1, %1};" : "=l"(wp) : "r"(__float_as_uint(w)));
            const ulonglong2 q0 = *(const ulonglong2*)&sS[d][0];   // broadcast
            const ulonglong2 q1 = *(const ulonglong2*)&sS[d][4];
            const ulonglong2 q2 = *(const ulonglong2*)&sS[d][8];
            const ulonglong2 q3 = *(const ulonglong2*)&sS[d][12];
            ffma2(acc[0], wp, q0.x);  ffma2(acc[1], wp, q0.y);
            ffma2(acc[2], wp, q1.x);  ffma2(acc[3], wp, q1.y);
            ffma2(acc[4], wp, q2.x);  ffma2(acc[5], wp, q2.y);
            ffma2(acc[6], wp, q3.x);  ffma2(acc[7], wp, q3.y);
        }
        __syncthreads();
    }

    // Store partial: 16 consecutive floats per o (4 STG.128).
    {
        float res[16];
#pragma unroll
        for (int j = 0; j < 8; ++j)
            asm("mov.b64 {%0, %1}, %2;"
                : "=f"(res[2 * j]), "=f"(res[2 * j + 1]) : "l"(acc[j]));
        float* dst = g_part + ((long)(c * KPARTS + kc) * OCH + t) * BATCH;
#pragma unroll
        for (int q = 0; q < 4; ++q)
            *(float4*)(dst + q * 4) =
                make_float4(res[q * 4], res[q * 4 + 1], res[q * 4 + 2], res[q * 4 + 3]);
    }

    __threadfence();
    __syncthreads();
    if (t == 0) s_ticket = atomicAdd(&g_cnt[c], 1);
    __syncthreads();

    if (s_ticket == KPARTS - 1) {
        // Last finisher reduces chunk c. Thread t owns o = obase + t.
        const float bo = bias[obase + t];
        float v[16];
#pragma unroll
        for (int b = 0; b < BATCH; ++b) v[b] = bo;

#pragma unroll 4
        for (int k2 = 0; k2 < KPARTS; ++k2) {
            const float4* p = (const float4*)(g_part
                              + ((long)(c * KPARTS + k2) * OCH + t) * BATCH);
#pragma unroll
            for (int q = 0; q < 4; ++q) {
                const float4 pv = __ldcg(p + q);
                v[q * 4 + 0] += pv.x;
                v[q * 4 + 1] += pv.y;
                v[q * 4 + 2] += pv.z;
                v[q * 4 + 3] += pv.w;
            }
        }
#pragma unroll
        for (int b = 0; b < BATCH; ++b)
            g_altered[b * DDIM + obase + t] = v[b];

        if (t == 0) g_cnt[c] = 0;   // self-reset for next graph replay
    }
}

// ---------------------------------------------------------------------------
// Kernel 2: weights[b][s] = sum_d altered[b][d] * enc[s][b][d]
// At the LTS chip cap (~6.3 TB/s) -- unchanged (proven 43.2us).
// ---------------------------------------------------------------------------
__global__ void __launch_bounds__(256, 8)
stage2_dots(const float* __restrict__ enc,
            float* __restrict__ out)
{
    __shared__ float alt[DDIM];

    const int tid    = threadIdx.x;
    const int warpId = tid >> 5;
    const int lane   = tid & 31;
    const int b      = blockIdx.y;
    const int s      = blockIdx.x * 8 + warpId;

#pragma unroll
    for (int j = 0; j < 2; ++j) {
        int f4 = tid + j * 256;
        *(float4*)&alt[f4 * 4] = *(const float4*)(g_altered + b * DDIM + f4 * 4);
    }
    __syncthreads();

    const float* row = enc + ((long)s * BATCH + b) * DDIM;

    float4 acc = make_float4(0.f, 0.f, 0.f, 0.f);
#pragma unroll
    for (int i = 0; i < 16; ++i) {
        const int d = i * 128 + lane * 4;
        const float4 e = *(const float4*)(row + d);
        const float4 a = *(const float4*)&alt[d];
        acc.x += e.x * a.x;
        acc.y += e.y * a.y;
        acc.z += e.z * a.z;
        acc.w += e.w * a.w;
    }

    float tt = (acc.x + acc.y) + (acc.z + acc.w);
#pragma unroll
    for (int off = 16; off > 0; off >>= 1)
        tt += __shfl_down_sync(0xFFFFFFFFu, tt, off);

    if (lane == 0)
        out[b * S_LEN + s] = tt;   // output shape [B, S]
}

extern "C" void kernel_launch(void* const* d_in, const int* in_sizes, int n_in,
                              void* d_out, int out_size)
{
    const float* enc   = (const float*)d_in[0];  // [S, B, D]
    const float* state = (const float*)d_in[1];  // [B, D]
    const float* W     = (const float*)d_in[2];  // [D, D]
    const float* bias  = (const float*)d_in[3];  // [D]
    float* out         = (float*)d_out;          // [B, S]

    stage1_fused<<<NCH * KPARTS, 128>>>(state, W, bias);
    stage2_dots<<<dim3(S_LEN / 8, BATCH), 256>>>(enc, out);
}

// round 9
// speedup vs baseline: 1.1308x; 1.1308x over previous
#include <cuda_runtime.h>
#include <cuda_bf16.h>
#include <cstdint>

// Problem shapes (fixed by the dataset)
#define S_LEN 2048
#define BATCH 16
#define DDIM  2048

// Stage-1 tiling: O_t=2, B_t=16 per thread -> 6 LDS per 64 MACs.
#define OTILE   256                 // o rows per block (2 per thread)
#define KSPLIT  64
#define KCHUNK  (DDIM / KSPLIT)     // 32 d per block
#define WPAD    33                  // sW bank = (r + d) % 32 -> conflict-free
#define SPAD    20                  // sS row stride (80B, 16B-aligned LDS.128)

// Scratch (device globals: allocation-free). g_part layout: [kc][o][b].
__device__ float g_part[KSPLIT * DDIM * BATCH];   // 8 MB
__device__ float g_altered[BATCH * DDIM];         // [b][o], 128 KB

__device__ __forceinline__ void ffma2(uint64_t& d, uint64_t a, uint64_t b) {
    asm("fma.rn.f32x2 %0, %1, %2, %0;" : "+l"(d) : "l"(a), "l"(b));
}

// ---------------------------------------------------------------------------
// Kernel 1a: partial[kc][o][b] = sum_{d in chunk kc} state[b][d] * W[o][d]
// Thread owns TWO o rows (t, t+128) x all 16 b. Per d: 2 scalar W LDS
// (banks (t+d)%32, conflict-free) + 4 broadcast state LDS.128 + 32 FFMA2.
// 6 LDS / 64 MACs = 3.3x better shared-pipe ratio than the 12.2us version,
// which sat exactly at the LDS crossbar floor. Grid 512 keeps 3-4 blocks/SM.
// ---------------------------------------------------------------------------
__global__ void __launch_bounds__(128)
stage1_part(const float* __restrict__ state,
            const float* __restrict__ W)
{
    __shared__ float sW[OTILE][WPAD];   // 256 x 33 x 4B = 33.8 KB
    __shared__ float sS[KCHUNK][SPAD];  // 2.5 KB

    const int t     = threadIdx.x;      // 0..127
    const int obase = blockIdx.x * OTILE;
    const int kc    = blockIdx.y;
    const int d0    = kc * KCHUNK;

    // --- Stage state chunk transposed: sS[d][b]. Coalesced float4 LDG.
    {
        const int b  = t >> 3;
        const int c4 = t & 7;
        const float4 v = *(const float4*)(state + b * DDIM + d0 + c4 * 4);
        sS[c4 * 4 + 0][b] = v.x;
        sS[c4 * 4 + 1][b] = v.y;
        sS[c4 * 4 + 2][b] = v.z;
        sS[c4 * 4 + 3][b] = v.w;
    }

    // --- Stage W tile 256 rows x 32 d: 2048 float4, 16/thread, coalesced
    // (8 lanes per row -> nL=4); STS banks (r + 4*c4 + k) % 32 conflict-free.
#pragma unroll
    for (int j = 0; j < 16; ++j) {
        const int g  = j * 128 + t;
        const int r  = g >> 3;
        const int c4 = g & 7;
        const float4 v = *(const float4*)(W + (long)(obase + r) * DDIM + d0 + c4 * 4);
        sW[r][c4 * 4 + 0] = v.x;
        sW[r][c4 * 4 + 1] = v.y;
        sW[r][c4 * 4 + 2] = v.z;
        sW[r][c4 * 4 + 3] = v.w;
    }
    __syncthreads();

    uint64_t acc0[8], acc1[8];          // 2 o-rows x 8 b-pairs (f32x2)
#pragma unroll
    for (int i = 0; i < 8; ++i) { acc0[i] = 0ull; acc1[i] = 0ull; }

#pragma unroll 8
    for (int d = 0; d < KCHUNK; ++d) {
        const float w0 = sW[t][d];             // bank (t+d)%32
        const float w1 = sW[t + 128][d];       // same pattern, conflict-free
        uint64_t wp0, wp1;
        asm("mov.b64 %0, {%1, %1};" : "=l"(wp0) : "r"(__float_as_uint(w0)));
        asm("mov.b64 %0, {%1, %1};" : "=l"(wp1) : "r"(__float_as_uint(w1)));
        const ulonglong2 q0 = *(const ulonglong2*)&sS[d][0];   // broadcast
        const ulonglong2 q1 = *(const ulonglong2*)&sS[d][4];
        const ulonglong2 q2 = *(const ulonglong2*)&sS[d][8];
        const ulonglong2 q3 = *(const ulonglong2*)&sS[d][12];
        ffma2(acc0[0], wp0, q0.x);  ffma2(acc0[1], wp0, q0.y);
        ffma2(acc0[2], wp0, q1.x);  ffma2(acc0[3], wp0, q1.y);
        ffma2(acc0[4], wp0, q2.x);  ffma2(acc0[5], wp0, q2.y);
        ffma2(acc0[6], wp0, q3.x);  ffma2(acc0[7], wp0, q3.y);
        ffma2(acc1[0], wp1, q0.x);  ffma2(acc1[1], wp1, q0.y);
        ffma2(acc1[2], wp1, q1.x);  ffma2(acc1[3], wp1, q1.y);
        ffma2(acc1[4], wp1, q2.x);  ffma2(acc1[5], wp1, q2.y);
        ffma2(acc1[6], wp1, q3.x);  ffma2(acc1[7], wp1, q3.y);
    }

    // --- Store both partial rows: 16 consecutive floats each (4 STG.128).
#pragma unroll
    for (int half = 0; half < 2; ++half) {
        const uint64_t* a = half ? acc1 : acc0;
        float res[16];
#pragma unroll
        for (int j = 0; j < 8; ++j)
            asm("mov.b64 {%0, %1}, %2;"
                : "=f"(res[2 * j]), "=f"(res[2 * j + 1]) : "l"(a[j]));
        const int o = obase + t + 128 * half;
        float* dst = g_part + ((long)kc * DDIM + o) * BATCH;
#pragma unroll
        for (int q = 0; q < 4; ++q)
            *(float4*)(dst + q * 4) =
                make_float4(res[q * 4], res[q * 4 + 1], res[q * 4 + 2], res[q * 4 + 3]);
    }
}

// ---------------------------------------------------------------------------
// Kernel 1b: altered[b][o] = bias[o] + sum_kc partial[kc][o][b]
// 8 MB streamed, coalesced, deterministic fixed-order sum.
// ---------------------------------------------------------------------------
__global__ void __launch_bounds__(256)
stage1_reduce(const float* __restrict__ bias)
{
    const int n = blockIdx.x * 256 + threadIdx.x;   // 0..32767
    const int o = n >> 4;
    const int b = n & 15;
    float v = bias[o];
#pragma unroll
    for (int kc = 0; kc < KSPLIT; ++kc)
        v += g_part[(long)kc * DDIM * BATCH + n];
    g_altered[b * DDIM + o] = v;
}

// ---------------------------------------------------------------------------
// Kernel 2: weights[b][s] = sum_d altered[b][d] * enc[s][b][d]
// enc is a 256 MB stream-once tensor -> __ldcs (evict-first) to keep L2
// ways free. Otherwise unchanged (proven at the ~6.4 TB/s LTS cap).
// ---------------------------------------------------------------------------
__global__ void __launch_bounds__(256, 8)
stage2_dots(const float* __restrict__ enc,
            float* __restrict__ out)
{
    __shared__ float alt[DDIM];

    const int tid    = threadIdx.x;
    const int warpId = tid >> 5;
    const int lane   = tid & 31;
    const int b      = blockIdx.y;
    const int s      = blockIdx.x * 8 + warpId;

#pragma unroll
    for (int j = 0; j < 2; ++j) {
        int f4 = tid + j * 256;
        *(float4*)&alt[f4 * 4] = *(const float4*)(g_altered + b * DDIM + f4 * 4);
    }
    __syncthreads();

    const float4* row = (const float4*)(enc + ((long)s * BATCH + b) * DDIM);

    float4 acc = make_float4(0.f, 0.f, 0.f, 0.f);
#pragma unroll
    for (int i = 0; i < 16; ++i) {
        const int f4 = i * 32 + lane;
        const float4 e = __ldcs(row + f4);          // streaming load
        const float4 a = *(const float4*)&alt[f4 * 4];
        acc.x += e.x * a.x;
        acc.y += e.y * a.y;
        acc.z += e.z * a.z;
        acc.w += e.w * a.w;
    }

    float tt = (acc.x + acc.y) + (acc.z + acc.w);
#pragma unroll
    for (int off = 16; off > 0; off >>= 1)
        tt += __shfl_down_sync(0xFFFFFFFFu, tt, off);

    if (lane == 0)
        out[b * S_LEN + s] = tt;   // output shape [B, S]
}

extern "C" void kernel_launch(void* const* d_in, const int* in_sizes, int n_in,
                              void* d_out, int out_size)
{
    const float* enc   = (const float*)d_in[0];  // [S, B, D]
    const float* state = (const float*)d_in[1];  // [B, D]
    const float* W     = (const float*)d_in[2];  // [D, D]
    const float* bias  = (const float*)d_in[3];  // [D]
    float* out         = (float*)d_out;          // [B, S]

    stage1_part<<<dim3(DDIM / OTILE, KSPLIT), 128>>>(state, W);
    stage1_reduce<<<(BATCH * DDIM) / 256, 256>>>(bias);
    stage2_dots<<<dim3(S_LEN / 8, BATCH), 256>>>(enc, out);
}